// round 1
// baseline (speedup 1.0000x reference)
#include <cuda_runtime.h>

// Problem constants
#define BSZ   64
#define NN    512
#define HID   128
#define NL    3
#define ECNT  16384
#define NCOL  8
#define EMBD  16
#define VOCAB 1000
#define ROWS  (BSZ * NN)      // 32768

// ---------------------------------------------------------------------------
// Scratch (static __device__ globals; no allocation anywhere)
// ---------------------------------------------------------------------------
__device__ float g_A[NN * NN];            // dense normalized adjacency, A[dst][src]
__device__ float g_deg[NN];
__device__ float g_X[ROWS * HID];         // entity-embedded input (t = 0 only)
__device__ float g_XW[ROWS * 2 * HID];    // [.,0:128]=x@Wz, [.,128:256]=x@Wh ; reused for gate lin out
__device__ float g_C[ROWS * 2 * HID];     // aggregated cz | ch
__device__ float g_H[ROWS * HID];         // Hn (next layer input)
__device__ float g_comb[BSZ * NL * HID];  // readout concat

// ---------------------------------------------------------------------------
// Graph normalization: deg (with self loops), dense A[dst*NN+src] = dinv_s*dinv_d
// ---------------------------------------------------------------------------
__global__ void k_zeroA() {
    int i = blockIdx.x * blockDim.x + threadIdx.x;
    if (i < NN * NN) g_A[i] = 0.f;
    if (i < NN) g_deg[i] = 1.f;   // self loop contributes 1 to deg
}

__global__ void k_deg(const int* __restrict__ edge) {
    int e = blockIdx.x * blockDim.x + threadIdx.x;
    if (e < ECNT) atomicAdd(&g_deg[edge[ECNT + e]], 1.f);
}

__global__ void k_buildA(const int* __restrict__ edge) {
    int e = blockIdx.x * blockDim.x + threadIdx.x;
    if (e < ECNT) {
        int s = edge[e];
        int d = edge[ECNT + e];
        atomicAdd(&g_A[d * NN + s], rsqrtf(g_deg[s]) * rsqrtf(g_deg[d]));
    } else if (e < ECNT + NN) {
        int n = e - ECNT;
        atomicAdd(&g_A[n * NN + n], 1.f / g_deg[n]);   // self loop: dinv^2
    }
}

// ---------------------------------------------------------------------------
// Entity embedding lookup: X[bn, c*16+j] = emb[c, x_seq[0, bn, c], j]
// ---------------------------------------------------------------------------
__global__ void k_embed(const int* __restrict__ xseq, const float* __restrict__ emb) {
    int t = blockIdx.x * blockDim.x + threadIdx.x;
    if (t >= ROWS * HID) return;
    int f  = t & 127;
    int bn = t >> 7;
    int c  = f >> 4;
    int j  = f & 15;
    int v  = xseq[bn * NCOL + c];
    g_X[t] = emb[(c * VOCAB + v) * EMBD + j];
}

// ---------------------------------------------------------------------------
// Generic batched SGEMM: C = A(MxK) * B(KxN) [+ bias per column]
// Tile 64x64, TK=16, 256 threads, 4x4 per thread. M,N,K multiples of 64/64/16.
// ---------------------------------------------------------------------------
__global__ void __launch_bounds__(256) k_gemm(
    int M, int N, int K,
    const float* __restrict__ Ag, int lda, long long sA,
    const float* __restrict__ Bg, int ldb, long long sB,
    float* __restrict__ Cg, int ldc, long long sC,
    const float* __restrict__ bias)
{
    const float* Ap = Ag + (long long)blockIdx.z * sA;
    const float* Bp = Bg + (long long)blockIdx.z * sB;
    float*       Cp = Cg + (long long)blockIdx.z * sC;

    const int tileN = blockIdx.x * 64;
    const int tileM = blockIdx.y * 64;

    __shared__ float As[16][65];   // padded: conflict-free STS along k
    __shared__ float Bs[16][64];

    const int tid = threadIdx.x;
    const int tx = tid & 15;       // n direction
    const int ty = tid >> 4;       // m direction

    float acc[4][4];
    #pragma unroll
    for (int i = 0; i < 4; i++)
        #pragma unroll
        for (int j = 0; j < 4; j++) acc[i][j] = 0.f;

    for (int k0 = 0; k0 < K; k0 += 16) {
        #pragma unroll
        for (int i = 0; i < 4; i++) {
            int idx = tid + i * 256;          // 0..1023
            int m = idx >> 4, k = idx & 15;
            As[k][m] = Ap[(long long)(tileM + m) * lda + (k0 + k)];
        }
        #pragma unroll
        for (int i = 0; i < 4; i++) {
            int idx = tid + i * 256;
            int k = idx >> 6, n = idx & 63;
            Bs[k][n] = Bp[(long long)(k0 + k) * ldb + (tileN + n)];
        }
        __syncthreads();

        #pragma unroll
        for (int k = 0; k < 16; k++) {
            float a[4], b[4];
            #pragma unroll
            for (int i = 0; i < 4; i++) a[i] = As[k][ty * 4 + i];
            #pragma unroll
            for (int j = 0; j < 4; j++) b[j] = Bs[k][tx * 4 + j];
            #pragma unroll
            for (int i = 0; i < 4; i++)
                #pragma unroll
                for (int j = 0; j < 4; j++)
                    acc[i][j] += a[i] * b[j];
        }
        __syncthreads();
    }

    #pragma unroll
    for (int i = 0; i < 4; i++) {
        long long crow = (long long)(tileM + ty * 4 + i) * ldc;
        #pragma unroll
        for (int j = 0; j < 4; j++) {
            int n = tileN + tx * 4 + j;
            float v = acc[i][j];
            if (bias) v += bias[n];
            Cp[crow + n] = v;
        }
    }
}

// ---------------------------------------------------------------------------
// GRU gate with H0 == 0:  Hn = (1 - sigmoid(zlin)) * tanh(hlin)
// zlin in g_XW[:, 0:128], hlin in g_XW[:, 128:256]
// ---------------------------------------------------------------------------
__global__ void k_gate() {
    int t = blockIdx.x * blockDim.x + threadIdx.x;
    if (t >= ROWS * HID) return;
    int r = t >> 7, o = t & 127;
    float zl = g_XW[r * 256 + o];
    float hl = g_XW[r * 256 + 128 + o];
    float z  = 1.f / (1.f + expf(-zl));
    g_H[t] = (1.f - z) * tanhf(hl);
}

// ---------------------------------------------------------------------------
// Readout: mean over nodes -> g_comb[b, l*128 + o]
// ---------------------------------------------------------------------------
__global__ void k_readout(int l) {
    int b = blockIdx.x;
    int o = threadIdx.x;   // 128 threads
    const float* base = g_H + (long long)b * NN * HID + o;
    float s = 0.f;
    for (int n = 0; n < NN; n++) s += base[n * HID];
    g_comb[b * (NL * HID) + l * HID + o] = s * (1.f / NN);
}

// ---------------------------------------------------------------------------
// Classifier: out = relu(comb @ W1 + b1) @ W2 + b2
// ---------------------------------------------------------------------------
__global__ void k_cls(const float* __restrict__ w1, const float* __restrict__ b1,
                      const float* __restrict__ w2, const float* __restrict__ b2,
                      float* __restrict__ out) {
    int b = blockIdx.x;    // 64
    int o = threadIdx.x;   // 128
    __shared__ float hid[HID];
    float s = b1[o];
    const float* cb = g_comb + b * (NL * HID);
    for (int k = 0; k < NL * HID; k++) s += cb[k] * w1[k * HID + o];
    hid[o] = fmaxf(s, 0.f);
    __syncthreads();
    if (o < 2) {
        float t = b2[o];
        for (int k = 0; k < HID; k++) t += hid[k] * w2[k * 2 + o];
        out[b * 2 + o] = t;
    }
}

// ---------------------------------------------------------------------------
// Launch
// ---------------------------------------------------------------------------
extern "C" void kernel_launch(void* const* d_in, const int* in_sizes, int n_in,
                              void* d_out, int out_size) {
    const int*   x_seq  = (const int*)  d_in[0];
    const int*   edge   = (const int*)  d_in[1];
    const float* emb    = (const float*)d_in[2];
    const float* conv_w = (const float*)d_in[3];
    const float* conv_b = (const float*)d_in[4];
    const float* lin_w  = (const float*)d_in[5];
    const float* lin_b  = (const float*)d_in[6];
    const float* w1     = (const float*)d_in[7];
    const float* b1     = (const float*)d_in[8];
    const float* w2     = (const float*)d_in[9];
    const float* b2     = (const float*)d_in[10];
    float* out = (float*)d_out;

    float *pA, *pX, *pXW, *pC, *pH;
    cudaGetSymbolAddress((void**)&pA,  g_A);
    cudaGetSymbolAddress((void**)&pX,  g_X);
    cudaGetSymbolAddress((void**)&pXW, g_XW);
    cudaGetSymbolAddress((void**)&pC,  g_C);
    cudaGetSymbolAddress((void**)&pH,  g_H);

    // Graph norm + dense adjacency
    k_zeroA<<<(NN * NN + 255) / 256, 256>>>();
    k_deg<<<(ECNT + 255) / 256, 256>>>(edge);
    k_buildA<<<(ECNT + NN + 255) / 256, 256>>>(edge);

    // Embedding lookup (t = 0 only)
    k_embed<<<(ROWS * HID + 255) / 256, 256>>>(x_seq, emb);

    const long long BSTRIDE = (long long)NN * 2 * HID;  // per-batch stride in XW / C

    for (int l = 0; l < NL; l++) {
        const float* xin = (l == 0) ? pX : pH;

        // XW: x_in @ conv_w[l,0] -> XW[:,0:128]; x_in @ conv_w[l,2] -> XW[:,128:256]
        k_gemm<<<dim3(2, 512, 1), 256>>>(ROWS, 128, 128,
            xin, 128, 0, conv_w + (l * 3 + 0) * 16384, 128, 0,
            pXW, 256, 0, nullptr);
        k_gemm<<<dim3(2, 512, 1), 256>>>(ROWS, 128, 128,
            xin, 128, 0, conv_w + (l * 3 + 2) * 16384, 128, 0,
            pXW + 128, 256, 0, nullptr);

        // Aggregation: per batch  C = A @ XW + conv_b   (A shared across batches)
        k_gemm<<<dim3(2, 8, 64), 256>>>(NN, 128, NN,
            pA, NN, 0, pXW, 256, BSTRIDE,
            pC, 256, BSTRIDE, conv_b + (l * 3 + 0) * 128);
        k_gemm<<<dim3(2, 8, 64), 256>>>(NN, 128, NN,
            pA, NN, 0, pXW + 128, 256, BSTRIDE,
            pC + 128, 256, BSTRIDE, conv_b + (l * 3 + 2) * 128);

        // Gate linears (only first 128 rows of lin_w matter; H0 == 0)
        k_gemm<<<dim3(2, 512, 1), 256>>>(ROWS, 128, 128,
            pC, 256, 0, lin_w + (l * 3 + 0) * 32768, 128, 0,
            pXW, 256, 0, lin_b + (l * 3 + 0) * 128);
        k_gemm<<<dim3(2, 512, 1), 256>>>(ROWS, 128, 128,
            pC + 128, 256, 0, lin_w + (l * 3 + 2) * 32768, 128, 0,
            pXW + 128, 256, 0, lin_b + (l * 3 + 2) * 128);

        // Hn = (1 - sigmoid(z)) * tanh(h)
        k_gate<<<(ROWS * HID + 255) / 256, 256>>>();

        // Node-mean readout into comb
        k_readout<<<BSZ, HID>>>(l);
    }

    // Classifier head
    k_cls<<<BSZ, HID>>>(w1, b1, w2, b2, out);
}

// round 4
// speedup vs baseline: 1.8453x; 1.8453x over previous
#include <cuda_runtime.h>

// Problem constants
#define BSZ   64
#define NN    512
#define HID   128
#define NL    3
#define ECNT  16384
#define NCOL  8
#define EMBD  16
#define VOCAB 1000
#define ROWS  (BSZ * NN)      // 32768
#define BF    (BSZ * HID)     // 8192  (node-major row width)

// ---------------------------------------------------------------------------
// Scratch (static __device__ globals; no allocation anywhere).
// __align__(16): these are accessed with float4 (LDG.128/STG.128); the float
// type alone only guarantees 4B alignment, and a misaligned 128-bit access
// traps (err715).
// Layout convention: node-major. X/AX/H are [NN, BSZ*HID] i.e. row (n*BSZ+b),
// which doubles as a [ROWS, HID] row-major matrix for per-row GEMMs.
// ---------------------------------------------------------------------------
__device__ __align__(16) float g_A[NN * NN];            // dense normalized adjacency A[dst][src]
__device__ __align__(16) float g_deg[NN];
__device__ __align__(16) float g_X[ROWS * HID];         // embedded input, node-major
__device__ __align__(16) float g_AX[ROWS * HID];        // A @ x_in, node-major
__device__ __align__(16) float g_ZH[ROWS * 2 * HID];    // [.,0:128]=zlin, [.,128:256]=hlin
__device__ __align__(16) float g_H[ROWS * HID];         // Hn, node-major
__device__ __align__(16) float g_Wm[NL * HID * 2 * HID];// merged weights [l][128][256] (z|h)
__device__ __align__(16) float g_bm[NL * 2 * HID];      // merged biases
__device__ __align__(16) float g_comb[BSZ * NL * HID];  // readout concat [b][l*128+f]

// ---------------------------------------------------------------------------
// Graph normalization
// ---------------------------------------------------------------------------
__global__ void k_zeroA() {
    int i = blockIdx.x * blockDim.x + threadIdx.x;
    if (i < NN * NN) g_A[i] = 0.f;
    if (i < NN) g_deg[i] = 1.f;   // self loop contributes 1
}

__global__ void k_deg(const int* __restrict__ edge) {
    int e = blockIdx.x * blockDim.x + threadIdx.x;
    if (e < ECNT) atomicAdd(&g_deg[edge[ECNT + e]], 1.f);
}

__global__ void k_buildA(const int* __restrict__ edge) {
    int e = blockIdx.x * blockDim.x + threadIdx.x;
    if (e < ECNT) {
        int s = edge[e];
        int d = edge[ECNT + e];
        atomicAdd(&g_A[d * NN + s], rsqrtf(g_deg[s]) * rsqrtf(g_deg[d]));
    } else if (e < ECNT + NN) {
        int n = e - ECNT;
        atomicAdd(&g_A[n * NN + n], 1.f / g_deg[n]);
    }
}

// ---------------------------------------------------------------------------
// Embedding lookup, node-major: X[(n*BSZ+b)*128 + c*16+j] = emb[c, xseq[b*NN+n, c], j]
// ---------------------------------------------------------------------------
__global__ void k_embed(const int* __restrict__ xseq, const float* __restrict__ emb) {
    int t = blockIdx.x * blockDim.x + threadIdx.x;
    if (t >= ROWS * HID) return;
    int f  = t & 127;
    int r  = t >> 7;          // n*BSZ + b
    int b  = r & (BSZ - 1);
    int n  = r >> 6;
    int c  = f >> 4;
    int j  = f & 15;
    int v  = xseq[(b * NN + n) * NCOL + c];
    g_X[t] = emb[(c * VOCAB + v) * EMBD + j];
}

// ---------------------------------------------------------------------------
// Small SGEMM (64x64 tile) — used for the 128x128x128 weight merges.
// Scalar loads only (safe for arbitrary harness pointers).
// ---------------------------------------------------------------------------
__global__ void __launch_bounds__(256) k_gemm64(
    int M, int N, int K,
    const float* __restrict__ Ag, int lda,
    const float* __restrict__ Bg, int ldb,
    float* __restrict__ Cg, int ldc)
{
    const int tileN = blockIdx.x * 64;
    const int tileM = blockIdx.y * 64;
    __shared__ float As[16][65];
    __shared__ float Bs[16][64];
    const int tid = threadIdx.x;
    const int tx = tid & 15, ty = tid >> 4;
    float acc[4][4] = {};
    for (int k0 = 0; k0 < K; k0 += 16) {
        #pragma unroll
        for (int i = 0; i < 4; i++) {
            int idx = tid + i * 256;
            int m = idx >> 4, k = idx & 15;
            As[k][m] = Ag[(long long)(tileM + m) * lda + (k0 + k)];
        }
        #pragma unroll
        for (int i = 0; i < 4; i++) {
            int idx = tid + i * 256;
            int k = idx >> 6, n = idx & 63;
            Bs[k][n] = Bg[(long long)(k0 + k) * ldb + (tileN + n)];
        }
        __syncthreads();
        #pragma unroll
        for (int k = 0; k < 16; k++) {
            float a[4], b[4];
            #pragma unroll
            for (int i = 0; i < 4; i++) a[i] = As[k][ty * 4 + i];
            #pragma unroll
            for (int j = 0; j < 4; j++) b[j] = Bs[k][tx * 4 + j];
            #pragma unroll
            for (int i = 0; i < 4; i++)
                #pragma unroll
                for (int j = 0; j < 4; j++) acc[i][j] += a[i] * b[j];
        }
        __syncthreads();
    }
    #pragma unroll
    for (int i = 0; i < 4; i++) {
        long long crow = (long long)(tileM + ty * 4 + i) * ldc;
        #pragma unroll
        for (int j = 0; j < 4; j++)
            Cg[crow + tileN + tx * 4 + j] = acc[i][j];
    }
}

// ---------------------------------------------------------------------------
// Main SGEMM: 128x128 tile, Ktile=8, 256 threads, 8x8/thread, double-buffered.
// Requires M%128==0, N%128==0, K%8==0, and 16B-aligned A/B/C with lda/ldb/ldc
// multiples of 4 (all call sites here qualify: device globals, aligned).
// ---------------------------------------------------------------------------
__global__ void __launch_bounds__(256) k_gemm128(
    int K,
    const float* __restrict__ A, int lda,
    const float* __restrict__ B, int ldb,
    float* __restrict__ C, int ldc,
    const float* __restrict__ bias)
{
    __shared__ float As[2][8][132];
    __shared__ float Bs[2][8][128];

    const int tid = threadIdx.x;
    const int tileM = blockIdx.y * 128;
    const int tileN = blockIdx.x * 128;

    // load assignments
    const int arow = tid >> 1;            // 0..127
    const int acol = (tid & 1) * 4;       // 0 or 4
    const int brow = tid >> 5;            // 0..7
    const int bcol = (tid & 31) * 4;      // 0..124

    const float* Aptr = A + (long long)(tileM + arow) * lda + acol;
    const float* Bptr = B + (long long)brow * ldb + tileN + bcol;
    const long long bstep = 8LL * ldb;

    const int ty = tid >> 4;              // 0..15
    const int tx = tid & 15;              // 0..15

    float acc[8][8];
    #pragma unroll
    for (int i = 0; i < 8; i++)
        #pragma unroll
        for (int j = 0; j < 8; j++) acc[i][j] = 0.f;

    const int KT = K >> 3;

    float4 aReg = *(const float4*)Aptr;
    float4 bReg = *(const float4*)Bptr;
    As[0][acol + 0][arow] = aReg.x;
    As[0][acol + 1][arow] = aReg.y;
    As[0][acol + 2][arow] = aReg.z;
    As[0][acol + 3][arow] = aReg.w;
    *(float4*)&Bs[0][brow][bcol] = bReg;
    __syncthreads();

    int buf = 0;
    for (int kt = 0; kt < KT; kt++) {
        if (kt + 1 < KT) {
            aReg = *(const float4*)(Aptr + (kt + 1) * 8);
            bReg = *(const float4*)(Bptr + (long long)(kt + 1) * bstep);
        }
        #pragma unroll
        for (int k = 0; k < 8; k++) {
            float4 a0 = *(float4*)&As[buf][k][ty * 8];
            float4 a1 = *(float4*)&As[buf][k][ty * 8 + 4];
            float4 b0 = *(float4*)&Bs[buf][k][tx * 8];
            float4 b1 = *(float4*)&Bs[buf][k][tx * 8 + 4];
            float av[8] = {a0.x, a0.y, a0.z, a0.w, a1.x, a1.y, a1.z, a1.w};
            float bv[8] = {b0.x, b0.y, b0.z, b0.w, b1.x, b1.y, b1.z, b1.w};
            #pragma unroll
            for (int i = 0; i < 8; i++)
                #pragma unroll
                for (int j = 0; j < 8; j++)
                    acc[i][j] += av[i] * bv[j];
        }
        if (kt + 1 < KT) {
            buf ^= 1;
            As[buf][acol + 0][arow] = aReg.x;
            As[buf][acol + 1][arow] = aReg.y;
            As[buf][acol + 2][arow] = aReg.z;
            As[buf][acol + 3][arow] = aReg.w;
            *(float4*)&Bs[buf][brow][bcol] = bReg;
            __syncthreads();
        }
    }

    float bv[8];
    #pragma unroll
    for (int j = 0; j < 8; j++)
        bv[j] = bias ? bias[tileN + tx * 8 + j] : 0.f;

    #pragma unroll
    for (int i = 0; i < 8; i++) {
        long long crow = (long long)(tileM + ty * 8 + i) * ldc + tileN + tx * 8;
        float4 v0 = {acc[i][0] + bv[0], acc[i][1] + bv[1], acc[i][2] + bv[2], acc[i][3] + bv[3]};
        float4 v1 = {acc[i][4] + bv[4], acc[i][5] + bv[5], acc[i][6] + bv[6], acc[i][7] + bv[7]};
        *(float4*)&C[crow]     = v0;
        *(float4*)&C[crow + 4] = v1;
    }
}

// ---------------------------------------------------------------------------
// Merged bias: bm[l][o] = lin_b[l,g][o'] + conv_b[l,g] @ lin_w[l,g][:128, o']
// g = 0 (z) for o<128, g = 2 (h) for o>=128
// ---------------------------------------------------------------------------
__global__ void k_bm(const float* __restrict__ conv_b,
                     const float* __restrict__ lin_w,
                     const float* __restrict__ lin_b) {
    int l = blockIdx.x;
    int o = threadIdx.x;              // 0..255
    int g = (o < 128) ? 0 : 2;
    int oo = o & 127;
    const float* cb = conv_b + (l * 3 + g) * 128;
    const float* lw = lin_w + (l * 3 + g) * 32768;
    float s = lin_b[(l * 3 + g) * 128 + oo];
    for (int k = 0; k < 128; k++) s += cb[k] * lw[k * 128 + oo];
    g_bm[l * 256 + o] = s;
}

// ---------------------------------------------------------------------------
// Gate (H0 == 0): Hn = (1 - sigmoid(zlin)) * tanh(hlin)
// ---------------------------------------------------------------------------
__global__ void k_gate() {
    int t = blockIdx.x * blockDim.x + threadIdx.x;
    if (t >= ROWS * HID) return;
    int r = t >> 7, o = t & 127;
    float zl = g_ZH[r * 256 + o];
    float hl = g_ZH[r * 256 + 128 + o];
    float z  = 1.f / (1.f + expf(-zl));
    g_H[t] = (1.f - z) * tanhf(hl);
}

// ---------------------------------------------------------------------------
// Readout: column means of the [NN, BSZ*HID] node-major H
// ---------------------------------------------------------------------------
__global__ void k_readout(int l) {
    int t = blockIdx.x * blockDim.x + threadIdx.x;   // 0..8191 = b*128 + f
    if (t >= BF) return;
    float s = 0.f;
    const float* base = g_H + t;
    for (int n = 0; n < NN; n++) s += base[(long long)n * BF];
    int b = t >> 7, f = t & 127;
    g_comb[b * (NL * HID) + l * HID + f] = s * (1.f / NN);
}

// ---------------------------------------------------------------------------
// Classifier: out = relu(comb @ W1 + b1) @ W2 + b2
// ---------------------------------------------------------------------------
__global__ void k_cls(const float* __restrict__ w1, const float* __restrict__ b1,
                      const float* __restrict__ w2, const float* __restrict__ b2,
                      float* __restrict__ out) {
    int b = blockIdx.x;
    int o = threadIdx.x;
    __shared__ float hid[HID];
    float s = b1[o];
    const float* cb = g_comb + b * (NL * HID);
    for (int k = 0; k < NL * HID; k++) s += cb[k] * w1[k * HID + o];
    hid[o] = fmaxf(s, 0.f);
    __syncthreads();
    if (o < 2) {
        float t = b2[o];
        for (int k = 0; k < HID; k++) t += hid[k] * w2[k * 2 + o];
        out[b * 2 + o] = t;
    }
}

// ---------------------------------------------------------------------------
// Launch
// ---------------------------------------------------------------------------
extern "C" void kernel_launch(void* const* d_in, const int* in_sizes, int n_in,
                              void* d_out, int out_size) {
    const int*   x_seq  = (const int*)  d_in[0];
    const int*   edge   = (const int*)  d_in[1];
    const float* emb    = (const float*)d_in[2];
    const float* conv_w = (const float*)d_in[3];
    const float* conv_b = (const float*)d_in[4];
    const float* lin_w  = (const float*)d_in[5];
    const float* lin_b  = (const float*)d_in[6];
    const float* w1     = (const float*)d_in[7];
    const float* b1     = (const float*)d_in[8];
    const float* w2     = (const float*)d_in[9];
    const float* b2     = (const float*)d_in[10];
    float* out = (float*)d_out;

    float *pA, *pX, *pAX, *pZH, *pH, *pWm, *pBm;
    cudaGetSymbolAddress((void**)&pA,  g_A);
    cudaGetSymbolAddress((void**)&pX,  g_X);
    cudaGetSymbolAddress((void**)&pAX, g_AX);
    cudaGetSymbolAddress((void**)&pZH, g_ZH);
    cudaGetSymbolAddress((void**)&pH,  g_H);
    cudaGetSymbolAddress((void**)&pWm, g_Wm);
    cudaGetSymbolAddress((void**)&pBm, g_bm);

    // Graph norm + dense adjacency
    k_zeroA<<<(NN * NN + 255) / 256, 256>>>();
    k_deg<<<(ECNT + 255) / 256, 256>>>(edge);
    k_buildA<<<(ECNT + NN + 255) / 256, 256>>>(edge);

    // Embedding lookup (t=0), node-major
    k_embed<<<(ROWS * HID + 255) / 256, 256>>>(x_seq, emb);

    // Weight merges: Wm[l][:,0:128] = Wz @ Lz_top ; Wm[l][:,128:256] = Wh @ Lh_top
    for (int l = 0; l < NL; l++) {
        k_gemm64<<<dim3(2, 2), 256>>>(128, 128, 128,
            conv_w + (l * 3 + 0) * 16384, 128,
            lin_w  + (l * 3 + 0) * 32768, 128,
            pWm + l * 32768, 256);
        k_gemm64<<<dim3(2, 2), 256>>>(128, 128, 128,
            conv_w + (l * 3 + 2) * 16384, 128,
            lin_w  + (l * 3 + 2) * 32768, 128,
            pWm + l * 32768 + 128, 256);
    }
    k_bm<<<NL, 256>>>(conv_b, lin_w, lin_b);

    for (int l = 0; l < NL; l++) {
        const float* xin = (l == 0) ? pX : pH;

        // AX = A @ x_in : [512, 8192] = [512,512] @ [512,8192]
        k_gemm128<<<dim3(BF / 128, NN / 128), 256>>>(NN,
            pA, NN, xin, BF, pAX, BF, nullptr);

        // ZH = AX_rows @ Wm[l] + bm[l] : [32768,256] = [32768,128] @ [128,256]
        k_gemm128<<<dim3(2, ROWS / 128), 256>>>(HID,
            pAX, HID, pWm + l * 32768, 256, pZH, 256, pBm + l * 256);

        // Hn = (1 - sigmoid(z)) * tanh(h)
        k_gate<<<(ROWS * HID + 255) / 256, 256>>>();

        // Node-mean readout
        k_readout<<<(BF + 255) / 256, 256>>>(l);
    }

    // Classifier head
    k_cls<<<BSZ, HID>>>(w1, b1, w2, b2, out);
}

// round 7
// speedup vs baseline: 2.9623x; 1.6054x over previous
#include <cuda_runtime.h>
#include <cuda_bf16.h>
#include <cstdint>

// Problem constants
#define BSZ   64
#define NN    512
#define HID   128
#define NL    3
#define ECNT  16384
#define NCOL  8
#define EMBD  16
#define VOCAB 1000
#define ROWS  (BSZ * NN)      // 32768
#define BF    (BSZ * HID)     // 8192

// ---------------------------------------------------------------------------
// Scratch (static __device__ globals; no allocation anywhere)
//   g_AX / g_H / g_ZH : [r, *] with r = node*64 + b
//   g_XT              : [j, n] with j = b*128 + f   (k-contiguous for GEMM1 B)
// GEMM1 output C[m=node][j] with ldc=8192 aliases g_AX[r=node*64+b][f] exactly.
// ---------------------------------------------------------------------------
__device__ __align__(16) float g_A[NN * NN];
__device__ __align__(16) float g_deg[NN];
__device__ __align__(16) float g_XT[BF * NN];
__device__ __align__(16) float g_AX[ROWS * HID];
__device__ __align__(16) float g_ZH[ROWS * 2 * HID];
__device__ __align__(16) float g_H[ROWS * HID];
__device__ __align__(16) float g_WmT[NL * 256 * HID];   // [l][o][i] k-contiguous
__device__ __align__(16) float g_bm[NL * 256];
__device__ __align__(16) float g_comb[BSZ * NL * HID];

// ---------------------------------------------------------------------------
// Helpers
// ---------------------------------------------------------------------------
__device__ __forceinline__ uint32_t s2u(const void* p) {
    uint32_t a;
    asm("{ .reg .u64 t; cvta.to.shared.u64 t, %1; cvt.u32.u64 %0, t; }" : "=r"(a) : "l"(p));
    return a;
}
__device__ __forceinline__ void ldsm4(uint32_t* r, uint32_t addr) {
    asm volatile("ldmatrix.sync.aligned.m8n8.x4.shared.b16 {%0,%1,%2,%3}, [%4];"
                 : "=r"(r[0]), "=r"(r[1]), "=r"(r[2]), "=r"(r[3]) : "r"(addr));
}
__device__ __forceinline__ void mma16816(float* d, const uint32_t* a, const uint32_t* b) {
    asm volatile(
        "mma.sync.aligned.m16n8k16.row.col.f32.bf16.bf16.f32 "
        "{%0,%1,%2,%3},{%4,%5,%6,%7},{%8,%9},{%0,%1,%2,%3};"
        : "+f"(d[0]), "+f"(d[1]), "+f"(d[2]), "+f"(d[3])
        : "r"(a[0]), "r"(a[1]), "r"(a[2]), "r"(a[3]), "r"(b[0]), "r"(b[1]));
}
// bf16 2-term split of a float4, stored to hi/lo smem arrays at elem offset pos
__device__ __forceinline__ void split_store(__nv_bfloat16* hi, __nv_bfloat16* lo,
                                            int pos, float4 v) {
    __nv_bfloat162 h0 = __float22bfloat162_rn(make_float2(v.x, v.y));
    __nv_bfloat162 h1 = __float22bfloat162_rn(make_float2(v.z, v.w));
    float2 f0 = __bfloat1622float2(h0), f1 = __bfloat1622float2(h1);
    __nv_bfloat162 l0 = __float22bfloat162_rn(make_float2(v.x - f0.x, v.y - f0.y));
    __nv_bfloat162 l1 = __float22bfloat162_rn(make_float2(v.z - f1.x, v.w - f1.y));
    *(__nv_bfloat162*)(hi + pos)     = h0;
    *(__nv_bfloat162*)(hi + pos + 2) = h1;
    *(__nv_bfloat162*)(lo + pos)     = l0;
    *(__nv_bfloat162*)(lo + pos + 2) = l1;
}

// ---------------------------------------------------------------------------
// Graph normalization + dense adjacency
// ---------------------------------------------------------------------------
__global__ void k_zeroA() {
    int i = blockIdx.x * blockDim.x + threadIdx.x;
    if (i < NN * NN) g_A[i] = 0.f;
    if (i < NN) g_deg[i] = 1.f;
}
__global__ void k_deg(const int* __restrict__ edge) {
    int e = blockIdx.x * blockDim.x + threadIdx.x;
    if (e < ECNT) atomicAdd(&g_deg[edge[ECNT + e]], 1.f);
}
__global__ void k_buildA(const int* __restrict__ edge) {
    int e = blockIdx.x * blockDim.x + threadIdx.x;
    if (e < ECNT) {
        int s = edge[e];
        int d = edge[ECNT + e];
        atomicAdd(&g_A[d * NN + s], rsqrtf(g_deg[s]) * rsqrtf(g_deg[d]));
    } else if (e < ECNT + NN) {
        int n = e - ECNT;
        atomicAdd(&g_A[n * NN + n], 1.f / g_deg[n]);
    }
}

// ---------------------------------------------------------------------------
// Embedding lookup straight into XT: XT[(b*128+f)*512+n] = emb[c, xseq[(b*512+n)*8+c], j]
// ---------------------------------------------------------------------------
__global__ void k_embed(const int* __restrict__ xseq, const float* __restrict__ emb) {
    int t = blockIdx.x * blockDim.x + threadIdx.x;
    if (t >= BF * NN) return;
    int n = t & 511;
    int j = t >> 9;
    int b = j >> 7;
    int f = j & 127;
    int c = f >> 4;
    int jj = f & 15;
    int v = xseq[(b * NN + n) * NCOL + c];
    g_XT[t] = emb[(c * VOCAB + v) * EMBD + jj];
}

// ---------------------------------------------------------------------------
// Transpose H[r,f] (r=n*64+b) -> XT[(b*128+f)*512 + n]
// ---------------------------------------------------------------------------
__global__ void k_trans() {
    __shared__ float sm[32][33];
    int b = blockIdx.z;
    int n0 = blockIdx.y * 32;
    int f0 = blockIdx.x * 32;
    int tx = threadIdx.x, ty = threadIdx.y;   // (32, 8)
    for (int yy = ty; yy < 32; yy += 8)
        sm[yy][tx] = g_H[(long long)((n0 + yy) * 64 + b) * 128 + f0 + tx];
    __syncthreads();
    for (int yy = ty; yy < 32; yy += 8)
        g_XT[(long long)(b * 128 + f0 + yy) * 512 + n0 + tx] = sm[tx][yy];
}

// ---------------------------------------------------------------------------
// Small SGEMM for weight merges (writes transposed): WmT[o][i]
// ---------------------------------------------------------------------------
__global__ void __launch_bounds__(256) k_gemm64(
    int K,
    const float* __restrict__ Ag, int lda,
    const float* __restrict__ Bg, int ldb,
    float* __restrict__ Cg, int ldc)
{
    const int tileN = blockIdx.x * 64;
    const int tileM = blockIdx.y * 64;
    __shared__ float As[16][65];
    __shared__ float Bs[16][64];
    const int tid = threadIdx.x;
    const int tx = tid & 15, ty = tid >> 4;
    float acc[4][4] = {};
    for (int k0 = 0; k0 < K; k0 += 16) {
        #pragma unroll
        for (int i = 0; i < 4; i++) {
            int idx = tid + i * 256;
            int m = idx >> 4, k = idx & 15;
            As[k][m] = Ag[(long long)(tileM + m) * lda + (k0 + k)];
        }
        #pragma unroll
        for (int i = 0; i < 4; i++) {
            int idx = tid + i * 256;
            int k = idx >> 6, n = idx & 63;
            Bs[k][n] = Bg[(long long)(k0 + k) * ldb + (tileN + n)];
        }
        __syncthreads();
        #pragma unroll
        for (int k = 0; k < 16; k++) {
            float a[4], b[4];
            #pragma unroll
            for (int i = 0; i < 4; i++) a[i] = As[k][ty * 4 + i];
            #pragma unroll
            for (int j = 0; j < 4; j++) b[j] = Bs[k][tx * 4 + j];
            #pragma unroll
            for (int i = 0; i < 4; i++)
                #pragma unroll
                for (int j = 0; j < 4; j++) acc[i][j] += a[i] * b[j];
        }
        __syncthreads();
    }
    #pragma unroll
    for (int i = 0; i < 4; i++)
        #pragma unroll
        for (int j = 0; j < 4; j++)
            Cg[(long long)(tileN + tx * 4 + j) * ldc + (tileM + ty * 4 + i)] = acc[i][j];
}

__global__ void k_bm(const float* __restrict__ conv_b,
                     const float* __restrict__ lin_w,
                     const float* __restrict__ lin_b) {
    int l = blockIdx.x;
    int o = threadIdx.x;
    int g = (o < 128) ? 0 : 2;
    int oo = o & 127;
    const float* cb = conv_b + (l * 3 + g) * 128;
    const float* lw = lin_w + (l * 3 + g) * 32768;
    float s = lin_b[(l * 3 + g) * 128 + oo];
    for (int k = 0; k < 128; k++) s += cb[k] * lw[k * 128 + oo];
    g_bm[l * 256 + o] = s;
}

// ---------------------------------------------------------------------------
// Tensor-core GEMM: C[m][n] = sum_k A[m][k]*B[n][k]  (+ bias[n])
// fp32 operands split to bf16 hi/lo on the fly; 3 MMA products (hh+hl+lh).
// CTA tile 128x128, K-chunk 32, 8 warps (2m x 4n), warp tile 64x32.
// Single static smem buffer (40KB) + register prefetch of the next chunk.
// ---------------------------------------------------------------------------
#define PITCH 40                 // bf16 elems per smem row (conflict-free ldmatrix)
#define ASZ   (128 * PITCH)      // 5120 elems per array

__global__ void __launch_bounds__(256) k_mma(
    const float* __restrict__ A, int lda,
    const float* __restrict__ B, int ldb,
    float* __restrict__ C, int ldc,
    int K, const float* __restrict__ bias)
{
    __shared__ __nv_bfloat16 sm[4 * ASZ];   // Ahi | Alo | Bhi | Blo  (40960 B)
    const int tid = threadIdx.x;
    const int lane = tid & 31, w = tid >> 5;
    const int wm = w & 1, wn = w >> 1;
    const int tileM = blockIdx.y * 128, tileN = blockIdx.x * 128;

    int lrow[4], lkq[4];
    #pragma unroll
    for (int i = 0; i < 4; i++) { int idx = tid + i * 256; lrow[i] = idx >> 3; lkq[i] = idx & 7; }

    const int KC = K >> 5;
    float4 ra[4], rb[4];
    #pragma unroll
    for (int i = 0; i < 4; i++) {
        ra[i] = *(const float4*)(A + (long long)(tileM + lrow[i]) * lda + lkq[i] * 4);
        rb[i] = *(const float4*)(B + (long long)(tileN + lrow[i]) * ldb + lkq[i] * 4);
    }

    float acc[4][4][4];
    #pragma unroll
    for (int i = 0; i < 4; i++)
        #pragma unroll
        for (int j = 0; j < 4; j++)
            #pragma unroll
            for (int q = 0; q < 4; q++) acc[i][j][q] = 0.f;

    const uint32_t sbase = s2u(sm);
    const int arow_l = wm * 64 + (lane & 15);
    const int acol_l = (lane >> 4) * 8;
    const int brow_l = wn * 32 + ((lane >> 4) & 1) * 8 + (lane & 7);
    const int bcol_l = ((lane >> 3) & 1) * 8;

    for (int c = 0; c < KC; c++) {
        // store current chunk (from registers) into smem
        #pragma unroll
        for (int i = 0; i < 4; i++) {
            int pos = lrow[i] * PITCH + lkq[i] * 4;
            split_store(sm,            sm + ASZ,     pos, ra[i]);
            split_store(sm + 2 * ASZ,  sm + 3 * ASZ, pos, rb[i]);
        }
        __syncthreads();

        // prefetch next chunk into registers (overlaps with MMA section)
        if (c + 1 < KC) {
            int kb = (c + 1) * 32;
            #pragma unroll
            for (int i = 0; i < 4; i++) {
                ra[i] = *(const float4*)(A + (long long)(tileM + lrow[i]) * lda + kb + lkq[i] * 4);
                rb[i] = *(const float4*)(B + (long long)(tileN + lrow[i]) * ldb + kb + lkq[i] * 4);
            }
        }

        #pragma unroll
        for (int s = 0; s < 2; s++) {
            uint32_t ah[4][4], bh[2][4], bl[2][4];
            #pragma unroll
            for (int i = 0; i < 4; i++)
                ldsm4(ah[i], sbase + (uint32_t)((arow_l + i * 16) * PITCH + acol_l + s * 16) * 2);
            #pragma unroll
            for (int p = 0; p < 2; p++)
                ldsm4(bh[p], sbase + 2 * ASZ * 2 + (uint32_t)((brow_l + p * 16) * PITCH + bcol_l + s * 16) * 2);
            #pragma unroll
            for (int i = 0; i < 4; i++)
                #pragma unroll
                for (int nt = 0; nt < 4; nt++)
                    mma16816(acc[i][nt], ah[i], &bh[nt >> 1][(nt & 1) * 2]);
            #pragma unroll
            for (int p = 0; p < 2; p++)
                ldsm4(bl[p], sbase + 3 * ASZ * 2 + (uint32_t)((brow_l + p * 16) * PITCH + bcol_l + s * 16) * 2);
            #pragma unroll
            for (int i = 0; i < 4; i++)
                #pragma unroll
                for (int nt = 0; nt < 4; nt++)
                    mma16816(acc[i][nt], ah[i], &bl[nt >> 1][(nt & 1) * 2]);
            #pragma unroll
            for (int i = 0; i < 4; i++)     // reuse ah regs for A-lo
                ldsm4(ah[i], sbase + ASZ * 2 + (uint32_t)((arow_l + i * 16) * PITCH + acol_l + s * 16) * 2);
            #pragma unroll
            for (int i = 0; i < 4; i++)
                #pragma unroll
                for (int nt = 0; nt < 4; nt++)
                    mma16816(acc[i][nt], ah[i], &bh[nt >> 1][(nt & 1) * 2]);
        }
        if (c + 1 < KC) __syncthreads();   // smem reused by next store
    }

    // Epilogue
    #pragma unroll
    for (int i = 0; i < 4; i++) {
        int m = tileM + wm * 64 + i * 16 + (lane >> 2);
        #pragma unroll
        for (int nt = 0; nt < 4; nt++) {
            int n = tileN + wn * 32 + nt * 8 + (lane & 3) * 2;
            float b0 = 0.f, b1 = 0.f;
            if (bias) { b0 = bias[n]; b1 = bias[n + 1]; }
            float2 v0 = {acc[i][nt][0] + b0, acc[i][nt][1] + b1};
            float2 v1 = {acc[i][nt][2] + b0, acc[i][nt][3] + b1};
            *(float2*)(C + (long long)m * ldc + n)       = v0;
            *(float2*)(C + (long long)(m + 8) * ldc + n) = v1;
        }
    }
}

// ---------------------------------------------------------------------------
// Gate (H0==0): Hn = (1 - sigmoid(zlin)) * tanh(hlin)
// ---------------------------------------------------------------------------
__global__ void k_gate() {
    int t = blockIdx.x * blockDim.x + threadIdx.x;
    if (t >= ROWS * HID) return;
    int r = t >> 7, o = t & 127;
    float zl = g_ZH[r * 256 + o];
    float hl = g_ZH[r * 256 + 128 + o];
    float z  = 1.f / (1.f + expf(-zl));
    g_H[t] = (1.f - z) * tanhf(hl);
}

// ---------------------------------------------------------------------------
// Readout + classifier
// ---------------------------------------------------------------------------
__global__ void k_readout(int l) {
    int t = blockIdx.x * blockDim.x + threadIdx.x;
    if (t >= BF) return;
    float s = 0.f;
    const float* base = g_H + t;
    for (int n = 0; n < NN; n++) s += base[(long long)n * BF];
    int b = t >> 7, f = t & 127;
    g_comb[b * (NL * HID) + l * HID + f] = s * (1.f / NN);
}

__global__ void k_cls(const float* __restrict__ w1, const float* __restrict__ b1,
                      const float* __restrict__ w2, const float* __restrict__ b2,
                      float* __restrict__ out) {
    int b = blockIdx.x;
    int o = threadIdx.x;
    __shared__ float hid[HID];
    float s = b1[o];
    const float* cb = g_comb + b * (NL * HID);
    for (int k = 0; k < NL * HID; k++) s += cb[k] * w1[k * HID + o];
    hid[o] = fmaxf(s, 0.f);
    __syncthreads();
    if (o < 2) {
        float t = b2[o];
        for (int k = 0; k < HID; k++) t += hid[k] * w2[k * 2 + o];
        out[b * 2 + o] = t;
    }
}

// ---------------------------------------------------------------------------
// Launch
// ---------------------------------------------------------------------------
extern "C" void kernel_launch(void* const* d_in, const int* in_sizes, int n_in,
                              void* d_out, int out_size) {
    const int*   x_seq  = (const int*)  d_in[0];
    const int*   edge   = (const int*)  d_in[1];
    const float* emb    = (const float*)d_in[2];
    const float* conv_w = (const float*)d_in[3];
    const float* conv_b = (const float*)d_in[4];
    const float* lin_w  = (const float*)d_in[5];
    const float* lin_b  = (const float*)d_in[6];
    const float* w1     = (const float*)d_in[7];
    const float* b1     = (const float*)d_in[8];
    const float* w2     = (const float*)d_in[9];
    const float* b2     = (const float*)d_in[10];
    float* out = (float*)d_out;

    float *pA, *pXT, *pAX, *pZH, *pWmT, *pBm;
    cudaGetSymbolAddress((void**)&pA,   g_A);
    cudaGetSymbolAddress((void**)&pXT,  g_XT);
    cudaGetSymbolAddress((void**)&pAX,  g_AX);
    cudaGetSymbolAddress((void**)&pZH,  g_ZH);
    cudaGetSymbolAddress((void**)&pWmT, g_WmT);
    cudaGetSymbolAddress((void**)&pBm,  g_bm);

    // Graph norm + dense adjacency
    k_zeroA<<<(NN * NN + 255) / 256, 256>>>();
    k_deg<<<(ECNT + 255) / 256, 256>>>(edge);
    k_buildA<<<(ECNT + NN + 255) / 256, 256>>>(edge);

    // Embedding (t=0) into XT layout
    k_embed<<<(BF * NN + 255) / 256, 256>>>(x_seq, emb);

    // Weight merges: WmT[l][o][i] = (conv_w[l,g] @ lin_w[l,g][:128])^T
    for (int l = 0; l < NL; l++) {
        k_gemm64<<<dim3(2, 2), 256>>>(128,
            conv_w + (l * 3 + 0) * 16384, 128,
            lin_w  + (l * 3 + 0) * 32768, 128,
            pWmT + l * 32768, 128);
        k_gemm64<<<dim3(2, 2), 256>>>(128,
            conv_w + (l * 3 + 2) * 16384, 128,
            lin_w  + (l * 3 + 2) * 32768, 128,
            pWmT + l * 32768 + 16384, 128);
    }
    k_bm<<<NL, 256>>>(conv_b, lin_w, lin_b);

    for (int l = 0; l < NL; l++) {
        if (l > 0)
            k_trans<<<dim3(4, 16, 64), dim3(32, 8)>>>();

        // GEMM1: AX[m=node][j] = A[m][n] * XT[j][n]^T   (M=512, N=8192, K=512)
        k_mma<<<dim3(64, 4), 256>>>(pA, NN, pXT, NN, pAX, BF, NN, nullptr);

        // GEMM2: ZH[r][o] = AX[r][k] * WmT[o][k]^T + bm  (M=32768, N=256, K=128)
        k_mma<<<dim3(2, 256), 256>>>(pAX, HID, pWmT + l * 32768, HID,
                                     pZH, 256, HID, pBm + l * 256);

        k_gate<<<(ROWS * HID + 255) / 256, 256>>>();
        k_readout<<<(BF + 255) / 256, 256>>>(l);
    }

    k_cls<<<BSZ, HID>>>(w1, b1, w2, b2, out);
}

// round 8
// speedup vs baseline: 3.8874x; 1.3123x over previous
#include <cuda_runtime.h>
#include <cuda_bf16.h>
#include <cstdint>

// Problem constants
#define BSZ   64
#define NN    512
#define HID   128
#define NL    3
#define ECNT  16384
#define NCOL  8
#define EMBD  16
#define VOCAB 1000
#define ROWS  (BSZ * NN)      // 32768
#define BF    (BSZ * HID)     // 8192

// ---------------------------------------------------------------------------
// Scratch. Activation layout: [n][j] with j = b*128 + f  (ld = 8192), which
// aliases [r][f] (r = n*64 + b) bit-exactly: n*8192 + b*128 + f.
// ---------------------------------------------------------------------------
__device__ __align__(16) float g_A[NN * NN];
__device__ __align__(16) float g_deg[NN];
__device__ __align__(16) float g_X[NN * BF];            // layer-0 input, [n][j]
__device__ __align__(16) float g_AX[ROWS * HID];        // A@x, [r][f] == [n][j]
__device__ __align__(16) float g_H[ROWS * HID];         // Hn,  [r][f] == [n][j]
__device__ __align__(16) float g_WmI[NL * 256 * HID];   // interleaved merged W: row 2f=z_f, 2f+1=h_f; cols i (k-contig)
__device__ __align__(16) float g_bm[NL * 256];          // interleaved merged bias
__device__ __align__(16) float g_comb[BSZ * NL * HID];

// ---------------------------------------------------------------------------
// Helpers
// ---------------------------------------------------------------------------
__device__ __forceinline__ uint32_t s2u(const void* p) {
    uint32_t a;
    asm("{ .reg .u64 t; cvta.to.shared.u64 t, %1; cvt.u32.u64 %0, t; }" : "=r"(a) : "l"(p));
    return a;
}
__device__ __forceinline__ void ldsm4(uint32_t* r, uint32_t addr) {
    asm volatile("ldmatrix.sync.aligned.m8n8.x4.shared.b16 {%0,%1,%2,%3}, [%4];"
                 : "=r"(r[0]), "=r"(r[1]), "=r"(r[2]), "=r"(r[3]) : "r"(addr));
}
__device__ __forceinline__ void ldsm4t(uint32_t* r, uint32_t addr) {
    asm volatile("ldmatrix.sync.aligned.m8n8.x4.trans.shared.b16 {%0,%1,%2,%3}, [%4];"
                 : "=r"(r[0]), "=r"(r[1]), "=r"(r[2]), "=r"(r[3]) : "r"(addr));
}
__device__ __forceinline__ void mma16816(float* d, const uint32_t* a, const uint32_t* b) {
    asm volatile(
        "mma.sync.aligned.m16n8k16.row.col.f32.bf16.bf16.f32 "
        "{%0,%1,%2,%3},{%4,%5,%6,%7},{%8,%9},{%0,%1,%2,%3};"
        : "+f"(d[0]), "+f"(d[1]), "+f"(d[2]), "+f"(d[3])
        : "r"(a[0]), "r"(a[1]), "r"(a[2]), "r"(a[3]), "r"(b[0]), "r"(b[1]));
}
__device__ __forceinline__ void split_store(__nv_bfloat16* hi, __nv_bfloat16* lo,
                                            int pos, float4 v) {
    __nv_bfloat162 h0 = __float22bfloat162_rn(make_float2(v.x, v.y));
    __nv_bfloat162 h1 = __float22bfloat162_rn(make_float2(v.z, v.w));
    float2 f0 = __bfloat1622float2(h0), f1 = __bfloat1622float2(h1);
    __nv_bfloat162 l0 = __float22bfloat162_rn(make_float2(v.x - f0.x, v.y - f0.y));
    __nv_bfloat162 l1 = __float22bfloat162_rn(make_float2(v.z - f1.x, v.w - f1.y));
    *(__nv_bfloat162*)(hi + pos)     = h0;
    *(__nv_bfloat162*)(hi + pos + 2) = h1;
    *(__nv_bfloat162*)(lo + pos)     = l0;
    *(__nv_bfloat162*)(lo + pos + 2) = l1;
}

// ---------------------------------------------------------------------------
// Graph normalization + dense adjacency
// ---------------------------------------------------------------------------
__global__ void k_zeroA() {
    int i = blockIdx.x * blockDim.x + threadIdx.x;
    if (i < NN * NN) g_A[i] = 0.f;
    if (i < NN) g_deg[i] = 1.f;
}
__global__ void k_deg(const int* __restrict__ edge) {
    int e = blockIdx.x * blockDim.x + threadIdx.x;
    if (e < ECNT) atomicAdd(&g_deg[edge[ECNT + e]], 1.f);
}
__global__ void k_buildA(const int* __restrict__ edge) {
    int e = blockIdx.x * blockDim.x + threadIdx.x;
    if (e < ECNT) {
        int s = edge[e];
        int d = edge[ECNT + e];
        atomicAdd(&g_A[d * NN + s], rsqrtf(g_deg[s]) * rsqrtf(g_deg[d]));
    } else if (e < ECNT + NN) {
        int n = e - ECNT;
        atomicAdd(&g_A[n * NN + n], 1.f / g_deg[n]);
    }
}

// ---------------------------------------------------------------------------
// Embedding lookup into [n][j]: X[n*8192 + b*128 + c*16 + jj]
// ---------------------------------------------------------------------------
__global__ void k_embed(const int* __restrict__ xseq, const float* __restrict__ emb) {
    int t = blockIdx.x * blockDim.x + threadIdx.x;
    if (t >= NN * BF) return;
    int n = t >> 13;
    int j = t & 8191;
    int b = j >> 7;
    int f = j & 127;
    int c = f >> 4;
    int jj = f & 15;
    int v = xseq[(b * NN + n) * NCOL + c];
    g_X[t] = emb[(c * VOCAB + v) * EMBD + jj];
}

// ---------------------------------------------------------------------------
// Small SGEMM for weight merges; writes C^T with interleaved rows:
// WmI[(o*2 + rowoff)][i]  (o = output col of the merge, i = input row)
// ---------------------------------------------------------------------------
__global__ void __launch_bounds__(256) k_gemm64(
    int K,
    const float* __restrict__ Ag, int lda,
    const float* __restrict__ Bg, int ldb,
    float* __restrict__ Cg, int rowoff)
{
    const int tileN = blockIdx.x * 64;
    const int tileM = blockIdx.y * 64;
    __shared__ float As[16][65];
    __shared__ float Bs[16][64];
    const int tid = threadIdx.x;
    const int tx = tid & 15, ty = tid >> 4;
    float acc[4][4] = {};
    for (int k0 = 0; k0 < K; k0 += 16) {
        #pragma unroll
        for (int i = 0; i < 4; i++) {
            int idx = tid + i * 256;
            int m = idx >> 4, k = idx & 15;
            As[k][m] = Ag[(long long)(tileM + m) * lda + (k0 + k)];
        }
        #pragma unroll
        for (int i = 0; i < 4; i++) {
            int idx = tid + i * 256;
            int k = idx >> 6, n = idx & 63;
            Bs[k][n] = Bg[(long long)(k0 + k) * ldb + (tileN + n)];
        }
        __syncthreads();
        #pragma unroll
        for (int k = 0; k < 16; k++) {
            float a[4], b[4];
            #pragma unroll
            for (int i = 0; i < 4; i++) a[i] = As[k][ty * 4 + i];
            #pragma unroll
            for (int j = 0; j < 4; j++) b[j] = Bs[k][tx * 4 + j];
            #pragma unroll
            for (int i = 0; i < 4; i++)
                #pragma unroll
                for (int j = 0; j < 4; j++) acc[i][j] += a[i] * b[j];
        }
        __syncthreads();
    }
    #pragma unroll
    for (int i = 0; i < 4; i++)
        #pragma unroll
        for (int j = 0; j < 4; j++)
            Cg[(long long)((tileN + tx * 4 + j) * 2 + rowoff) * 128 + (tileM + ty * 4 + i)] = acc[i][j];
}

// Merged bias, interleaved: bm[2f+g'] ; g'=0 -> z (gate 0), g'=1 -> h (gate 2)
__global__ void k_bm(const float* __restrict__ conv_b,
                     const float* __restrict__ lin_w,
                     const float* __restrict__ lin_b) {
    int l = blockIdx.x;
    int o = threadIdx.x;              // 0..255
    int f = o >> 1;
    int gg = (o & 1) ? 2 : 0;
    const float* cb = conv_b + (l * 3 + gg) * 128;
    const float* lw = lin_w + (l * 3 + gg) * 32768;
    float s = lin_b[(l * 3 + gg) * 128 + f];
    for (int k = 0; k < 128; k++) s += cb[k] * lw[k * 128 + f];
    g_bm[l * 256 + o] = s;
}

// ---------------------------------------------------------------------------
// Tensor-core GEMM, templated:
//  BTRANS=0: B global [n][k] (k-contig), normal ldmatrix
//  BTRANS=1: B global [k][n] (n-contig), ldmatrix.trans
//  FUSEGATE=1: N=256 interleaved z|h; epilogue computes H=(1-sig(z))*tanh(h),
//              writes C[m*ldc + n/2]
// C = A[m][k] * B^T (+bias). CTA tile 128x128(FUSE:256? no—128 N cols per tile),
// K-chunk 16, double-buffered, one __syncthreads per chunk.
// ---------------------------------------------------------------------------
#define PA 24
#define ASZE (128 * PA)          // 3072 elems

template<int BTRANS, int FUSEGATE>
__global__ void __launch_bounds__(256) k_mma(
    const float* __restrict__ A, int lda,
    const float* __restrict__ B, int ldb,
    float* __restrict__ C, int ldc,
    int K, const float* __restrict__ bias)
{
    constexpr int PB   = BTRANS ? 136 : 24;
    constexpr int BSZE = BTRANS ? 16 * 136 : 128 * 24;
    __shared__ __align__(16) __nv_bfloat16 smA[2][2][ASZE];
    __shared__ __align__(16) __nv_bfloat16 smB[2][2][BSZE];

    const int tid = threadIdx.x;
    const int lane = tid & 31, w = tid >> 5;
    const int wm = w & 1, wn = w >> 1;
    const int tileM = blockIdx.y * 128, tileN = blockIdx.x * 128;

    // load assignments (2 float4 per operand per thread per 16-K chunk)
    int arow[2], akq[2], brow[2], bcq[2];
    #pragma unroll
    for (int i = 0; i < 2; i++) {
        int idx = tid + i * 256;       // 0..511
        arow[i] = idx >> 2;  akq[i] = idx & 3;         // A: 128 rows x 4 f4
        if (BTRANS) { brow[i] = idx >> 5; bcq[i] = idx & 31; }  // B: 16 rows x 32 f4
        else        { brow[i] = idx >> 2; bcq[i] = idx & 3;  }  // B: 128 rows x 4 f4
    }

    const int KC = K >> 4;
    float4 ra[2], rb[2];
    #pragma unroll
    for (int i = 0; i < 2; i++) {
        ra[i] = *(const float4*)(A + (long long)(tileM + arow[i]) * lda + akq[i] * 4);
        if (BTRANS)
            rb[i] = *(const float4*)(B + (long long)brow[i] * ldb + tileN + bcq[i] * 4);
        else
            rb[i] = *(const float4*)(B + (long long)(tileN + brow[i]) * ldb + bcq[i] * 4);
    }

    float acc[4][4][4];
    #pragma unroll
    for (int i = 0; i < 4; i++)
        #pragma unroll
        for (int j = 0; j < 4; j++)
            #pragma unroll
            for (int q = 0; q < 4; q++) acc[i][j][q] = 0.f;

    const uint32_t sa0 = s2u(&smA[0][0][0]);
    const uint32_t sb0 = s2u(&smB[0][0][0]);
    const int arow_l = wm * 64 + (lane & 15);
    const int acol_l = (lane >> 4) * 8;
    // B non-trans lane mapping
    const int brow_l = wn * 32 + ((lane >> 4) & 1) * 8 + (lane & 7);
    const int bcol_l = ((lane >> 3) & 1) * 8;
    // B trans lane mapping: rows = k, cols = n
    const int tkrow_l = ((lane >> 3) & 1) * 8 + (lane & 7);
    const int tnoff_l = wn * 32 + ((lane >> 4) & 1) * 8;

    // prologue: store chunk 0 into buffer 0
    #pragma unroll
    for (int i = 0; i < 2; i++) {
        split_store(smA[0][0], smA[0][1], arow[i] * PA + akq[i] * 4, ra[i]);
        int posb = BTRANS ? (brow[i] * PB + bcq[i] * 4) : (brow[i] * PB + bcq[i] * 4);
        split_store(smB[0][0], smB[0][1], posb, rb[i]);
    }

    for (int c = 0; c < KC; c++) {
        __syncthreads();
        const int buf = c & 1;
        if (c + 1 < KC) {
            int kb = (c + 1) * 16;
            #pragma unroll
            for (int i = 0; i < 2; i++) {
                ra[i] = *(const float4*)(A + (long long)(tileM + arow[i]) * lda + kb + akq[i] * 4);
                if (BTRANS)
                    rb[i] = *(const float4*)(B + (long long)(kb + brow[i]) * ldb + tileN + bcq[i] * 4);
                else
                    rb[i] = *(const float4*)(B + (long long)(tileN + brow[i]) * ldb + kb + bcq[i] * 4);
            }
        }

        const uint32_t ba = sa0 + buf * (2 * ASZE * 2);
        const uint32_t bb = sb0 + buf * (2 * BSZE * 2);
        uint32_t ah[4][4], bh[2][4], bl[2][4];
        #pragma unroll
        for (int i = 0; i < 4; i++)
            ldsm4(ah[i], ba + (uint32_t)((arow_l + i * 16) * PA + acol_l) * 2);
        #pragma unroll
        for (int p = 0; p < 2; p++) {
            if (BTRANS) {
                ldsm4t(bh[p], bb + (uint32_t)(tkrow_l * PB + tnoff_l + p * 16) * 2);
                ldsm4t(bl[p], bb + (uint32_t)(BSZE * 2) + (uint32_t)(tkrow_l * PB + tnoff_l + p * 16) * 2);
            } else {
                ldsm4(bh[p], bb + (uint32_t)((brow_l + p * 16) * PB + bcol_l) * 2);
                ldsm4(bl[p], bb + (uint32_t)(BSZE * 2) + (uint32_t)((brow_l + p * 16) * PB + bcol_l) * 2);
            }
        }
        #pragma unroll
        for (int i = 0; i < 4; i++)
            #pragma unroll
            for (int nt = 0; nt < 4; nt++)
                mma16816(acc[i][nt], ah[i], &bh[nt >> 1][(nt & 1) * 2]);
        #pragma unroll
        for (int i = 0; i < 4; i++)
            #pragma unroll
            for (int nt = 0; nt < 4; nt++)
                mma16816(acc[i][nt], ah[i], &bl[nt >> 1][(nt & 1) * 2]);
        #pragma unroll
        for (int i = 0; i < 4; i++)     // reuse ah for A-lo
            ldsm4(ah[i], ba + (uint32_t)(ASZE * 2) + (uint32_t)((arow_l + i * 16) * PA + acol_l) * 2);
        #pragma unroll
        for (int i = 0; i < 4; i++)
            #pragma unroll
            for (int nt = 0; nt < 4; nt++)
                mma16816(acc[i][nt], ah[i], &bh[nt >> 1][(nt & 1) * 2]);

        if (c + 1 < KC) {
            const int nb = buf ^ 1;
            #pragma unroll
            for (int i = 0; i < 2; i++) {
                split_store(smA[nb][0], smA[nb][1], arow[i] * PA + akq[i] * 4, ra[i]);
                split_store(smB[nb][0], smB[nb][1], brow[i] * PB + bcq[i] * 4, rb[i]);
            }
        }
    }

    // Epilogue
    if (FUSEGATE) {
        #pragma unroll
        for (int i = 0; i < 4; i++) {
            int m = tileM + wm * 64 + i * 16 + (lane >> 2);
            #pragma unroll
            for (int nt = 0; nt < 4; nt++) {
                int n = tileN + wn * 32 + nt * 8 + (lane & 3) * 2;
                int f = n >> 1;
                float bz = bias[n], bh2 = bias[n + 1];
                float zl = acc[i][nt][0] + bz;
                float hl = acc[i][nt][1] + bh2;
                float z = 1.f / (1.f + expf(-zl));
                C[(long long)m * ldc + f] = (1.f - z) * tanhf(hl);
                zl = acc[i][nt][2] + bz;
                hl = acc[i][nt][3] + bh2;
                z = 1.f / (1.f + expf(-zl));
                C[(long long)(m + 8) * ldc + f] = (1.f - z) * tanhf(hl);
            }
        }
    } else {
        #pragma unroll
        for (int i = 0; i < 4; i++) {
            int m = tileM + wm * 64 + i * 16 + (lane >> 2);
            #pragma unroll
            for (int nt = 0; nt < 4; nt++) {
                int n = tileN + wn * 32 + nt * 8 + (lane & 3) * 2;
                float b0 = 0.f, b1 = 0.f;
                if (bias) { b0 = bias[n]; b1 = bias[n + 1]; }
                float2 v0 = {acc[i][nt][0] + b0, acc[i][nt][1] + b1};
                float2 v1 = {acc[i][nt][2] + b0, acc[i][nt][3] + b1};
                *(float2*)(C + (long long)m * ldc + n)       = v0;
                *(float2*)(C + (long long)(m + 8) * ldc + n) = v1;
            }
        }
    }
}

// ---------------------------------------------------------------------------
// Readout + classifier
// ---------------------------------------------------------------------------
__global__ void k_readout(int l) {
    int t = blockIdx.x * blockDim.x + threadIdx.x;   // j = b*128+f
    if (t >= BF) return;
    float s = 0.f;
    const float* base = g_H + t;
    for (int n = 0; n < NN; n++) s += base[(long long)n * BF];
    int b = t >> 7, f = t & 127;
    g_comb[b * (NL * HID) + l * HID + f] = s * (1.f / NN);
}

__global__ void k_cls(const float* __restrict__ w1, const float* __restrict__ b1,
                      const float* __restrict__ w2, const float* __restrict__ b2,
                      float* __restrict__ out) {
    int b = blockIdx.x;
    int o = threadIdx.x;
    __shared__ float hid[HID];
    float s = b1[o];
    const float* cb = g_comb + b * (NL * HID);
    for (int k = 0; k < NL * HID; k++) s += cb[k] * w1[k * HID + o];
    hid[o] = fmaxf(s, 0.f);
    __syncthreads();
    if (o < 2) {
        float t = b2[o];
        for (int k = 0; k < HID; k++) t += hid[k] * w2[k * 2 + o];
        out[b * 2 + o] = t;
    }
}

// ---------------------------------------------------------------------------
// Launch
// ---------------------------------------------------------------------------
extern "C" void kernel_launch(void* const* d_in, const int* in_sizes, int n_in,
                              void* d_out, int out_size) {
    const int*   x_seq  = (const int*)  d_in[0];
    const int*   edge   = (const int*)  d_in[1];
    const float* emb    = (const float*)d_in[2];
    const float* conv_w = (const float*)d_in[3];
    const float* conv_b = (const float*)d_in[4];
    const float* lin_w  = (const float*)d_in[5];
    const float* lin_b  = (const float*)d_in[6];
    const float* w1     = (const float*)d_in[7];
    const float* b1     = (const float*)d_in[8];
    const float* w2     = (const float*)d_in[9];
    const float* b2     = (const float*)d_in[10];
    float* out = (float*)d_out;

    float *pA, *pX, *pAX, *pH, *pWmI, *pBm;
    cudaGetSymbolAddress((void**)&pA,   g_A);
    cudaGetSymbolAddress((void**)&pX,   g_X);
    cudaGetSymbolAddress((void**)&pAX,  g_AX);
    cudaGetSymbolAddress((void**)&pH,   g_H);
    cudaGetSymbolAddress((void**)&pWmI, g_WmI);
    cudaGetSymbolAddress((void**)&pBm,  g_bm);

    // Graph norm + dense adjacency
    k_zeroA<<<(NN * NN + 255) / 256, 256>>>();
    k_deg<<<(ECNT + 255) / 256, 256>>>(edge);
    k_buildA<<<(ECNT + NN + 255) / 256, 256>>>(edge);

    // Embedding (t=0), [n][j] layout
    k_embed<<<(NN * BF + 255) / 256, 256>>>(x_seq, emb);

    // Weight merges -> interleaved WmI rows (2f = z, 2f+1 = h)
    for (int l = 0; l < NL; l++) {
        k_gemm64<<<dim3(2, 2), 256>>>(128,
            conv_w + (l * 3 + 0) * 16384, 128,
            lin_w  + (l * 3 + 0) * 32768, 128,
            pWmI + l * 32768, 0);
        k_gemm64<<<dim3(2, 2), 256>>>(128,
            conv_w + (l * 3 + 2) * 16384, 128,
            lin_w  + (l * 3 + 2) * 32768, 128,
            pWmI + l * 32768, 1);
    }
    k_bm<<<NL, 256>>>(conv_b, lin_w, lin_b);

    for (int l = 0; l < NL; l++) {
        const float* xin = (l == 0) ? pX : pH;   // [n][j], ld 8192

        // GEMM1: AX[m=node][j] = sum_n A[m][n] * Xin[n][j]   (M=512,N=8192,K=512)
        k_mma<1, 0><<<dim3(64, 4), 256>>>(pA, NN, xin, BF, pAX, BF, NN, nullptr);

        // GEMM2 + fused gate: H[r][f]  (M=32768, N=256 interleaved, K=128)
        k_mma<0, 1><<<dim3(2, 256), 256>>>(pAX, HID, pWmI + l * 32768, HID,
                                           pH, HID, HID, pBm + l * 256);

        k_readout<<<(BF + 255) / 256, 256>>>(l);
    }

    k_cls<<<BSZ, HID>>>(w1, b1, w2, b2, out);
}